// round 1
// baseline (speedup 1.0000x reference)
#include <cuda_runtime.h>

#define Bb   2
#define Ss   1024
#define Hh   768
#define Dd   24
#define Kk   96
#define VIN  2304
#define VHID 768

// ---------------- scratch (static device allocations — allowed) ----------------
__device__ float g_Zj[Bb * Ss * Dd];
__device__ float g_Zi[Bb * Ss * Dd];
__device__ float g_CJ[Bb * Ss * Kk];
__device__ float g_CI[Bb * Ss * Kk];
__device__ float g_probs[(size_t)Bb * Ss * Ss];
__device__ float g_ctx[Bb * Ss * Hh];
__device__ float g_hid[Bb * Ss * VHID];

// ---------------- packed f32x2 helpers (Blackwell) ----------------
__device__ __forceinline__ unsigned long long ffma2(unsigned long long a, unsigned long long b,
                                                    unsigned long long c) {
    unsigned long long d;
    asm("fma.rn.f32x2 %0, %1, %2, %3;" : "=l"(d) : "l"(a), "l"(b), "l"(c));
    return d;
}
__device__ __forceinline__ unsigned long long fadd2(unsigned long long a, unsigned long long b) {
    unsigned long long d;
    asm("add.rn.f32x2 %0, %1, %2;" : "=l"(d) : "l"(a), "l"(b));
    return d;
}
__device__ __forceinline__ unsigned long long fpack2(float lo, float hi) {
    unsigned long long d;
    asm("mov.b64 %0, {%1, %2};" : "=l"(d) : "f"(lo), "f"(hi));
    return d;
}
__device__ __forceinline__ float2 funpack2(unsigned long long a) {
    float2 r;
    asm("mov.b64 {%0, %1}, %2;" : "=f"(r.x), "=f"(r.y) : "l"(a));
    return r;
}

// ================= K1: Zj, Zi, cj = b1 + Zj@W1a, ci = Zi@W1b =================
__global__ __launch_bounds__(128) void k1_prep(const float* __restrict__ Hj,
                                               const float* __restrict__ Hi,
                                               const float* __restrict__ Wpj,
                                               const float* __restrict__ Wpi,
                                               const float* __restrict__ W1,
                                               const float* __restrict__ b1) {
    int bs  = blockIdx.x;
    int tid = threadIdx.x;
    int w   = tid >> 5, l = tid & 31;
    __shared__ float part[4][Dd];
    __shared__ float zjs[Dd], zis[Dd];

    const float* Hrow = (w < 2 ? Hj : Hi) + (size_t)bs * Hh;
    const float* Wp   = (w < 2 ? Wpj : Wpi);
    if (l < Dd) {
        float acc = 0.f;
        int h0 = (w & 1) * (Hh / 2);
#pragma unroll 4
        for (int h = h0; h < h0 + Hh / 2; ++h)
            acc = fmaf(Hrow[h], Wp[h * Dd + l], acc);
        part[w][l] = acc;
    }
    __syncthreads();
    if (tid < Dd) {
        float z = part[0][tid] + part[1][tid];
        zjs[tid] = z;
        g_Zj[bs * Dd + tid] = z;
    }
    if (tid >= 32 && tid < 32 + Dd) {
        int d = tid - 32;
        float z = part[2][d] + part[3][d];
        zis[d] = z;
        g_Zi[bs * Dd + d] = z;
    }
    __syncthreads();
    if (tid < Kk) {
        float cj = b1[tid], ci = 0.f;
#pragma unroll
        for (int d = 0; d < Dd; ++d) {
            cj = fmaf(zjs[d], W1[d * Kk + tid], cj);
            ci = fmaf(zis[d], W1[(Dd + d) * Kk + tid], ci);
        }
        g_CJ[bs * Kk + tid] = cj;
        g_CI[bs * Kk + tid] = ci;
    }
}

// ================= K2: pairwise logits + softmax -> probs =================
// block = one (b,s) row, 128 threads; thread handles t = tile*128 + tid.
__global__ __launch_bounds__(128) void k2_pair(const float* __restrict__ W1,
                                               const float* __restrict__ W2,
                                               const float* __restrict__ mask) {
    int bs  = blockIdx.x;
    int b   = bs >> 10;
    int tid = threadIdx.x;

    __shared__ __align__(16) float w1c_t[Kk][Dd];  // [k][d]
    __shared__ __align__(16) float w1d_t[Kk][Dd];
    __shared__ float w2s[Kk], cjs[Kk], zjs[Dd];
    __shared__ float zis[128][25];  // pad 25 -> conflict-free row reads
    __shared__ float lg[Ss];
    __shared__ float red[4];

    for (int idx = tid; idx < Kk * Dd; idx += 128) {
        int k = idx / Dd, d = idx - k * Dd;
        w1c_t[k][d] = W1[(2 * Dd + d) * Kk + k];
        w1d_t[k][d] = W1[(3 * Dd + d) * Kk + k];
    }
    if (tid < Kk) {
        w2s[tid] = W2[tid];
        cjs[tid] = g_CJ[bs * Kk + tid];
    }
    if (tid < Dd) zjs[tid] = g_Zj[bs * Dd + tid];
    __syncthreads();

    const float* ciBase = g_CI + (size_t)b * Ss * Kk;
    const float* ziBase = g_Zi + (size_t)b * Ss * Dd;

    for (int tile = 0; tile < Ss / 128; ++tile) {
        int t0 = tile * 128;
        for (int idx = tid; idx < 128 * Dd; idx += 128) {
            int tl = idx / Dd, d = idx - tl * Dd;
            zis[tl][d] = ziBase[(size_t)(t0 + tl) * Dd + d];
        }
        __syncthreads();

        // per-pair features packed as f32x2
        unsigned long long prod[Dd / 2], adf[Dd / 2];
#pragma unroll
        for (int d2 = 0; d2 < Dd / 2; ++d2) {
            float z0 = zjs[2 * d2], z1 = zjs[2 * d2 + 1];
            float i0 = zis[tid][2 * d2], i1 = zis[tid][2 * d2 + 1];
            prod[d2] = fpack2(z0 * i0, z1 * i1);
            adf[d2]  = fpack2(fabsf(z0 - i0), fabsf(z1 - i1));
        }
        const float* ciRow = ciBase + (size_t)(t0 + tid) * Kk;
        float logit = 0.f;
#pragma unroll 2
        for (int k = 0; k < Kk; k += 2) {
            float2 ci2 = *(const float2*)(ciRow + k);
            const ulonglong2* wc0 = (const ulonglong2*)(&w1c_t[k][0]);
            const ulonglong2* wd0 = (const ulonglong2*)(&w1d_t[k][0]);
            const ulonglong2* wc1 = (const ulonglong2*)(&w1c_t[k + 1][0]);
            const ulonglong2* wd1 = (const ulonglong2*)(&w1d_t[k + 1][0]);
            unsigned long long a0 = 0ull, e0 = 0ull, a1 = 0ull, e1 = 0ull;
#pragma unroll
            for (int q = 0; q < Dd / 4; ++q) {
                ulonglong2 c0 = wc0[q], d0 = wd0[q], c1 = wc1[q], d1 = wd1[q];
                a0 = ffma2(prod[2 * q], c0.x, a0);
                a0 = ffma2(prod[2 * q + 1], c0.y, a0);
                e0 = ffma2(adf[2 * q], d0.x, e0);
                e0 = ffma2(adf[2 * q + 1], d0.y, e0);
                a1 = ffma2(prod[2 * q], c1.x, a1);
                a1 = ffma2(prod[2 * q + 1], c1.y, a1);
                e1 = ffma2(adf[2 * q], d1.x, e1);
                e1 = ffma2(adf[2 * q + 1], d1.y, e1);
            }
            float2 s0 = funpack2(fadd2(a0, e0));
            float2 s1 = funpack2(fadd2(a1, e1));
            float h0 = (s0.x + s0.y) + (cjs[k] + ci2.x);
            float h1 = (s1.x + s1.y) + (cjs[k + 1] + ci2.y);
            h0 = fmaxf(h0, 0.f);
            h1 = fmaxf(h1, 0.f);
            logit = fmaf(h0, w2s[k], logit);
            logit = fmaf(h1, w2s[k + 1], logit);
        }
        float m = mask[b * Ss + t0 + tid];
        logit += (1.0f - m) * (-3.402823466e38f);
        lg[t0 + tid] = logit;
        __syncthreads();
    }

    // softmax over lg[0..1023]  (b2 is constant across t -> cancels)
    float mx = -3.402823466e38f;
    for (int i = tid; i < Ss; i += 128) mx = fmaxf(mx, lg[i]);
#pragma unroll
    for (int o = 16; o; o >>= 1) mx = fmaxf(mx, __shfl_xor_sync(0xffffffffu, mx, o));
    if ((tid & 31) == 0) red[tid >> 5] = mx;
    __syncthreads();
    mx = fmaxf(fmaxf(red[0], red[1]), fmaxf(red[2], red[3]));
    __syncthreads();

    float sum = 0.f;
    for (int i = tid; i < Ss; i += 128) {
        float e = __expf(lg[i] - mx);
        lg[i] = e;
        sum += e;
    }
#pragma unroll
    for (int o = 16; o; o >>= 1) sum += __shfl_xor_sync(0xffffffffu, sum, o);
    if ((tid & 31) == 0) red[tid >> 5] = sum;
    __syncthreads();
    sum = (red[0] + red[1]) + (red[2] + red[3]);
    float inv = 1.0f / sum;

    float* orow = g_probs + (size_t)bs * Ss;
    for (int i = tid; i < Ss; i += 128) orow[i] = lg[i] * inv;
}

// ================= GEMM template: 128x64 tile, 8x4 microtile (f32x2) =================
// MODE 0: ctx = probs @ H_i  (batched over blockIdx.z)
// MODE 1: hid = relu(msg_in @ Wv1 + bv1), msg_in built on the fly
// MODE 2: out = alpha * (hid @ Wv2 + bv2)
__device__ __forceinline__ float load_msgin(int r, int c, const float* __restrict__ Hj) {
    if (c < Hh) return g_ctx[(size_t)r * Hh + c];
    if (c < 2 * Hh) return Hj[(size_t)r * Hh + (c - Hh)];
    int cc = c - 2 * Hh;
    return g_ctx[(size_t)r * Hh + cc] * Hj[(size_t)r * Hh + cc];
}

template <int MODE>
__global__ __launch_bounds__(256) void gemm_kernel(const float* __restrict__ Ap,
                                                   const float* __restrict__ Bp,
                                                   const float* __restrict__ Hj,
                                                   const float* __restrict__ bias,
                                                   const float* __restrict__ alpha,
                                                   float* __restrict__ Cp, int Kdim, int lda,
                                                   int ldb) {
    int m0 = blockIdx.x * 128;
    int n0 = blockIdx.y * 64;
    const float* A = Ap;
    const float* Bm = Bp;
    float* C = Cp;
    if (MODE == 0) {
        int b = blockIdx.z;
        A += (size_t)b * Ss * Ss;
        Bm += (size_t)b * Ss * Hh;
        C += (size_t)b * Ss * Hh;
    }

    __shared__ __align__(16) float As[128][33];
    __shared__ __align__(16) float Bs[32][64];
    const int tid = threadIdx.x;
    const int mg = tid & 15;   // rows mg + i*16 (strided -> conflict-free column LDS)
    const int ng = tid >> 4;   // cols ng*4 .. ng*4+3
    unsigned long long acc[8][2];
#pragma unroll
    for (int i = 0; i < 8; ++i) {
        acc[i][0] = 0ull;
        acc[i][1] = 0ull;
    }

    for (int k0 = 0; k0 < Kdim; k0 += 32) {
        __syncthreads();
#pragma unroll
        for (int r = 0; r < 16; ++r) {  // 128*32 / 256
            int idx = r * 256 + tid;
            int ml = idx >> 5, kl = idx & 31;
            int kc = k0 + kl;
            float v;
            if (MODE == 1)
                v = load_msgin(m0 + ml, kc, Hj);
            else
                v = A[(size_t)(m0 + ml) * lda + kc];
            As[ml][kl] = v;
        }
#pragma unroll
        for (int r = 0; r < 8; ++r) {  // 32*64 / 256
            int idx = r * 256 + tid;
            int kl = idx >> 6, nl = idx & 63;
            Bs[kl][nl] = Bm[(size_t)(k0 + kl) * ldb + n0 + nl];
        }
        __syncthreads();
#pragma unroll 8
        for (int kk = 0; kk < 32; ++kk) {
            ulonglong2 bb = *(const ulonglong2*)(&Bs[kk][ng * 4]);
#pragma unroll
            for (int i = 0; i < 8; ++i) {
                float av = As[mg + i * 16][kk];
                unsigned long long aa = fpack2(av, av);
                acc[i][0] = ffma2(aa, bb.x, acc[i][0]);
                acc[i][1] = ffma2(aa, bb.y, acc[i][1]);
            }
        }
    }

    float4 bias4 = make_float4(0.f, 0.f, 0.f, 0.f);
    if (MODE != 0) bias4 = *(const float4*)(&bias[n0 + ng * 4]);
    float al = (MODE == 2) ? alpha[0] : 0.f;

#pragma unroll
    for (int i = 0; i < 8; ++i) {
        float2 v0 = funpack2(acc[i][0]);
        float2 v1 = funpack2(acc[i][1]);
        float4 o = make_float4(v0.x, v0.y, v1.x, v1.y);
        if (MODE == 1) {
            o.x = fmaxf(o.x + bias4.x, 0.f);
            o.y = fmaxf(o.y + bias4.y, 0.f);
            o.z = fmaxf(o.z + bias4.z, 0.f);
            o.w = fmaxf(o.w + bias4.w, 0.f);
        } else if (MODE == 2) {
            o.x = al * (o.x + bias4.x);
            o.y = al * (o.y + bias4.y);
            o.z = al * (o.z + bias4.z);
            o.w = al * (o.w + bias4.w);
        }
        *(float4*)(&C[(size_t)(m0 + mg + i * 16) * Hh + n0 + ng * 4]) = o;
    }
}

// ================= launch =================
extern "C" void kernel_launch(void* const* d_in, const int* in_sizes, int n_in, void* d_out,
                              int out_size) {
    const float* Hj   = (const float*)d_in[0];
    const float* Hi   = (const float*)d_in[1];
    const float* mask = (const float*)d_in[2];
    const float* Wpj  = (const float*)d_in[3];
    const float* Wpi  = (const float*)d_in[4];
    const float* W1   = (const float*)d_in[5];
    const float* b1   = (const float*)d_in[6];
    const float* W2   = (const float*)d_in[7];
    // d_in[8] = b2: constant shift of all logits -> cancels in softmax
    const float* Wv1   = (const float*)d_in[9];
    const float* bv1   = (const float*)d_in[10];
    const float* Wv2   = (const float*)d_in[11];
    const float* bv2   = (const float*)d_in[12];
    const float* alpha = (const float*)d_in[13];
    float* out = (float*)d_out;

    float* d_probs = nullptr;
    float* d_ctx = nullptr;
    float* d_hid = nullptr;
    cudaGetSymbolAddress((void**)&d_probs, g_probs);
    cudaGetSymbolAddress((void**)&d_ctx, g_ctx);
    cudaGetSymbolAddress((void**)&d_hid, g_hid);

    k1_prep<<<Bb * Ss, 128>>>(Hj, Hi, Wpj, Wpi, W1, b1);
    k2_pair<<<Bb * Ss, 128>>>(W1, W2, mask);
    gemm_kernel<0><<<dim3(Ss / 128, Hh / 64, Bb), 256>>>(d_probs, Hi, nullptr, nullptr, nullptr,
                                                         d_ctx, Ss, Ss, Hh);
    gemm_kernel<1><<<dim3(Bb * Ss / 128, VHID / 64), 256>>>(nullptr, Wv1, Hj, bv1, nullptr, d_hid,
                                                            VIN, 0, VHID);
    gemm_kernel<2><<<dim3(Bb * Ss / 128, Hh / 64), 256>>>(d_hid, Wv2, nullptr, bv2, alpha, out,
                                                          VHID, VHID, Hh);
}

// round 3
// speedup vs baseline: 1.6550x; 1.6550x over previous
#include <cuda_runtime.h>

#define Bb   2
#define Ss   1024
#define Hh   768
#define Dd   24
#define Kk   96
#define VIN  2304
#define VHID 768

// ---------------- scratch ----------------
__device__ float g_Zj[Bb * Ss * Dd];
__device__ float g_Zi[Bb * Ss * Dd];
__device__ float g_CJ[Bb * Ss * Kk];
__device__ float g_CI[Bb * Ss * Kk];
__device__ float g_probs[(size_t)Bb * Ss * Ss];
__device__ float g_ctx[Bb * Ss * Hh];
__device__ float g_ctxh[Bb * Ss * Hh];
__device__ float g_hid[Bb * Ss * VHID];

__device__ __forceinline__ unsigned long long ffma2(unsigned long long a, unsigned long long b,
                                                    unsigned long long c) {
    unsigned long long d;
    asm("fma.rn.f32x2 %0, %1, %2, %3;" : "=l"(d) : "l"(a), "l"(b), "l"(c));
    return d;
}
__device__ __forceinline__ unsigned long long fpack2(float lo, float hi) {
    unsigned long long d;
    asm("mov.b64 %0, {%1, %2};" : "=l"(d) : "f"(lo), "f"(hi));
    return d;
}
__device__ __forceinline__ float2 funpack2(unsigned long long a) {
    float2 r;
    asm("mov.b64 {%0, %1}, %2;" : "=f"(r.x), "=f"(r.y) : "l"(a));
    return r;
}

// ================= K1: Zj, Zi, cj = b1 + Zj@W1a, ci = Zi@W1b =================
__global__ __launch_bounds__(128) void k1_prep(const float* __restrict__ Hj,
                                               const float* __restrict__ Hi,
                                               const float* __restrict__ Wpj,
                                               const float* __restrict__ Wpi,
                                               const float* __restrict__ W1,
                                               const float* __restrict__ b1) {
    int bs  = blockIdx.x;
    int tid = threadIdx.x;
    int w   = tid >> 5, l = tid & 31;
    __shared__ float part[4][Dd];
    __shared__ float zjs[Dd], zis[Dd];

    const float* Hrow = (w < 2 ? Hj : Hi) + (size_t)bs * Hh;
    const float* Wp   = (w < 2 ? Wpj : Wpi);
    if (l < Dd) {
        float acc = 0.f;
        int h0 = (w & 1) * (Hh / 2);
#pragma unroll 4
        for (int h = h0; h < h0 + Hh / 2; ++h)
            acc = fmaf(Hrow[h], Wp[h * Dd + l], acc);
        part[w][l] = acc;
    }
    __syncthreads();
    if (tid < Dd) {
        float z = part[0][tid] + part[1][tid];
        zjs[tid] = z;
        g_Zj[bs * Dd + tid] = z;
    }
    if (tid >= 32 && tid < 32 + Dd) {
        int d = tid - 32;
        float z = part[2][d] + part[3][d];
        zis[d] = z;
        g_Zi[bs * Dd + d] = z;
    }
    __syncthreads();
    if (tid < Kk) {
        float cj = b1[tid], ci = 0.f;
#pragma unroll
        for (int d = 0; d < Dd; ++d) {
            cj = fmaf(zjs[d], W1[d * Kk + tid], cj);
            ci = fmaf(zis[d], W1[(Dd + d) * Kk + tid], ci);
        }
        g_CJ[bs * Kk + tid] = cj;
        g_CI[bs * Kk + tid] = ci;
    }
}

// ================= K2: pairwise logits + softmax -> probs =================
__global__ __launch_bounds__(128) void k2_pair(const float* __restrict__ W1,
                                               const float* __restrict__ W2,
                                               const float* __restrict__ mask) {
    int bs  = blockIdx.x;
    int b   = bs >> 10;
    int tid = threadIdx.x;

    __shared__ __align__(16) float w1c_t[Kk][Dd];  // row = 96 B, 16B aligned
    __shared__ __align__(16) float w1d_t[Kk][Dd];
    __shared__ float w2s[Kk], cjs[Kk], zjs[Dd];
    __shared__ float lg[Ss];
    __shared__ float red[4];

    for (int idx = tid; idx < Kk * Dd; idx += 128) {
        int k = idx / Dd, d = idx - k * Dd;
        w1c_t[k][d] = W1[(2 * Dd + d) * Kk + k];
        w1d_t[k][d] = W1[(3 * Dd + d) * Kk + k];
    }
    if (tid < Kk) {
        w2s[tid] = W2[tid];
        cjs[tid] = g_CJ[bs * Kk + tid];
    }
    if (tid < Dd) zjs[tid] = g_Zj[bs * Dd + tid];
    __syncthreads();

    float zj[Dd];
#pragma unroll
    for (int d = 0; d < Dd; ++d) zj[d] = zjs[d];

    const float* ciBase = g_CI + (size_t)b * Ss * Kk;
    const float* ziBase = g_Zi + (size_t)b * Ss * Dd;

#pragma unroll 1
    for (int it = 0; it < 4; ++it) {
        int ta = it * 256 + tid * 2;
        int tb = ta + 1;

        float zA[Dd], zB[Dd];
        {
            const float4* ra = (const float4*)(ziBase + (size_t)ta * Dd);  // 96B stride: aligned
            const float4* rb = (const float4*)(ziBase + (size_t)tb * Dd);
#pragma unroll
            for (int q = 0; q < Dd / 4; ++q) {
                float4 va = ra[q], vb = rb[q];
                zA[4 * q] = va.x; zA[4 * q + 1] = va.y; zA[4 * q + 2] = va.z; zA[4 * q + 3] = va.w;
                zB[4 * q] = vb.x; zB[4 * q + 1] = vb.y; zB[4 * q + 2] = vb.z; zB[4 * q + 3] = vb.w;
            }
        }
        unsigned long long pa[Dd / 2], aa[Dd / 2], pb[Dd / 2], ab[Dd / 2];
#pragma unroll
        for (int q = 0; q < Dd / 2; ++q) {
            float j0 = zj[2 * q], j1 = zj[2 * q + 1];
            pa[q] = fpack2(j0 * zA[2 * q], j1 * zA[2 * q + 1]);
            aa[q] = fpack2(fabsf(j0 - zA[2 * q]), fabsf(j1 - zA[2 * q + 1]));
            pb[q] = fpack2(j0 * zB[2 * q], j1 * zB[2 * q + 1]);
            ab[q] = fpack2(fabsf(j0 - zB[2 * q]), fabsf(j1 - zB[2 * q + 1]));
        }

        const float* ciA = ciBase + (size_t)ta * Kk;  // 384B stride: aligned
        const float* ciB = ciBase + (size_t)tb * Kk;
        float logitA = 0.f, logitB = 0.f;

#pragma unroll 1
        for (int k4 = 0; k4 < Kk; k4 += 4) {
            float4 cA4 = *(const float4*)(ciA + k4);
            float4 cB4 = *(const float4*)(ciB + k4);
            float cAv[4] = {cA4.x, cA4.y, cA4.z, cA4.w};
            float cBv[4] = {cB4.x, cB4.y, cB4.z, cB4.w};
#pragma unroll
            for (int j = 0; j < 4; ++j) {
                int k = k4 + j;
                const ulonglong2* wc = (const ulonglong2*)(&w1c_t[k][0]);
                const ulonglong2* wd = (const ulonglong2*)(&w1d_t[k][0]);
                unsigned long long sA = 0ull, sB = 0ull;
#pragma unroll
                for (int u = 0; u < 6; ++u) {
                    ulonglong2 c = wc[u];  // feature pairs 2u, 2u+1
                    sA = ffma2(pa[2 * u], c.x, sA);
                    sA = ffma2(pa[2 * u + 1], c.y, sA);
                    sB = ffma2(pb[2 * u], c.x, sB);
                    sB = ffma2(pb[2 * u + 1], c.y, sB);
                }
#pragma unroll
                for (int u = 0; u < 6; ++u) {
                    ulonglong2 c = wd[u];
                    sA = ffma2(aa[2 * u], c.x, sA);
                    sA = ffma2(aa[2 * u + 1], c.y, sA);
                    sB = ffma2(ab[2 * u], c.x, sB);
                    sB = ffma2(ab[2 * u + 1], c.y, sB);
                }
                float2 uA = funpack2(sA);
                float2 uB = funpack2(sB);
                float hA = (uA.x + uA.y) + (cjs[k] + cAv[j]);
                float hB = (uB.x + uB.y) + (cjs[k] + cBv[j]);
                hA = fmaxf(hA, 0.f);
                hB = fmaxf(hB, 0.f);
                logitA = fmaf(hA, w2s[k], logitA);
                logitB = fmaf(hB, w2s[k], logitB);
            }
        }
        float mA = mask[b * Ss + ta];
        float mB = mask[b * Ss + tb];
        lg[ta] = logitA + (1.0f - mA) * (-3.402823466e38f);
        lg[tb] = logitB + (1.0f - mB) * (-3.402823466e38f);
    }
    __syncthreads();

    float mx = -3.402823466e38f;
    for (int i = tid; i < Ss; i += 128) mx = fmaxf(mx, lg[i]);
#pragma unroll
    for (int o = 16; o; o >>= 1) mx = fmaxf(mx, __shfl_xor_sync(0xffffffffu, mx, o));
    if ((tid & 31) == 0) red[tid >> 5] = mx;
    __syncthreads();
    mx = fmaxf(fmaxf(red[0], red[1]), fmaxf(red[2], red[3]));
    __syncthreads();

    float sum = 0.f;
    for (int i = tid; i < Ss; i += 128) {
        float e = __expf(lg[i] - mx);
        lg[i] = e;
        sum += e;
    }
#pragma unroll
    for (int o = 16; o; o >>= 1) sum += __shfl_xor_sync(0xffffffffu, sum, o);
    if ((tid & 31) == 0) red[tid >> 5] = sum;
    __syncthreads();
    sum = (red[0] + red[1]) + (red[2] + red[3]);
    float inv = 1.0f / sum;

    float* orow = g_probs + (size_t)bs * Ss;
    for (int i = tid; i < Ss; i += 128) orow[i] = lg[i] * inv;
}

// ================= GEMM: 128x64 tile, 256 thr, 8x4 micro, double-buffered =================
// MODE 0: ctx = probs @ H_i (per b); epilogue also writes ctxh = ctx * Hj
// MODE 1: hid = relu([ctx|Hj|ctxh] @ Wv1 + bv1)
// MODE 2: out = alpha * (hid @ Wv2 + bv2)
template <int MODE>
__global__ __launch_bounds__(256) void gemm_kernel(const float* __restrict__ Ap,
                                                   const float* __restrict__ Bp,
                                                   const float* __restrict__ Hjp,
                                                   const float* __restrict__ bias,
                                                   const float* __restrict__ alpha,
                                                   float* __restrict__ Cp, int Kdim, int lda) {
    const int m0 = blockIdx.x * 128;
    const int n0 = blockIdx.y * 64;
    const float* A = Ap;
    const float* Bm = Bp;
    float* C = Cp;
    size_t rowbase = 0;
    if (MODE == 0) {
        int b = blockIdx.z;
        A += (size_t)b * Ss * Ss;
        Bm += (size_t)b * Ss * Hh;
        C += (size_t)b * Ss * Hh;
        rowbase = (size_t)b * Ss;
    }

    // As pad 17 => conflict-free strided column LDS; stores are SCALAR (68B row
    // stride is not 16B aligned — STS.128 here traps with misaligned address).
    __shared__ float As[2][128][17];
    __shared__ __align__(16) float Bs[2][16][64];  // 256B rows: STS/LDS.128 aligned

    const int tid = threadIdx.x;
    const int mg = tid & 15;
    const int ng = tid >> 4;
    const int ar0 = tid >> 2, ac = (tid & 3) * 4;
    const int ar1 = ar0 + 64;
    const int bkl = tid >> 4, bnl = (tid & 15) * 4;

    unsigned long long acc[8][2];
#pragma unroll
    for (int i = 0; i < 8; ++i) { acc[i][0] = 0ull; acc[i][1] = 0ull; }

    const int nkt = Kdim / 16;

    auto storeA = [&](int buf, int row, const float4& v) {
        As[buf][row][ac]     = v.x;
        As[buf][row][ac + 1] = v.y;
        As[buf][row][ac + 2] = v.z;
        As[buf][row][ac + 3] = v.w;
    };

    float4 ra0, ra1, rb0;
    {
        int kc = ac;
        if (MODE == 1) {
            ra0 = *(const float4*)(g_ctx + (size_t)(m0 + ar0) * Hh + kc);
            ra1 = *(const float4*)(g_ctx + (size_t)(m0 + ar1) * Hh + kc);
        } else {
            ra0 = *(const float4*)(A + (size_t)(m0 + ar0) * lda + kc);
            ra1 = *(const float4*)(A + (size_t)(m0 + ar1) * lda + kc);
        }
        rb0 = *(const float4*)(Bm + (size_t)bkl * Hh + n0 + bnl);
    }
    storeA(0, ar0, ra0);
    storeA(0, ar1, ra1);
    *(float4*)(&Bs[0][bkl][bnl]) = rb0;
    __syncthreads();

#pragma unroll 1
    for (int kt = 0; kt < nkt; ++kt) {
        const int cur = kt & 1;
        if (kt + 1 < nkt) {
            int k0 = (kt + 1) * 16;
            int kc = k0 + ac;
            if (MODE == 1) {
                int seg = kc / Hh;
                const float* base = (seg == 0) ? g_ctx : (seg == 1) ? Hjp : g_ctxh;
                int kq = kc - seg * Hh;
                ra0 = *(const float4*)(base + (size_t)(m0 + ar0) * Hh + kq);
                ra1 = *(const float4*)(base + (size_t)(m0 + ar1) * Hh + kq);
            } else {
                ra0 = *(const float4*)(A + (size_t)(m0 + ar0) * lda + kc);
                ra1 = *(const float4*)(A + (size_t)(m0 + ar1) * lda + kc);
            }
            rb0 = *(const float4*)(Bm + (size_t)(k0 + bkl) * Hh + n0 + bnl);
        }
#pragma unroll
        for (int kk = 0; kk < 16; ++kk) {
            ulonglong2 bb = *(const ulonglong2*)(&Bs[cur][kk][ng * 4]);
#pragma unroll
            for (int i = 0; i < 8; ++i) {
                float av = As[cur][mg + i * 16][kk];
                unsigned long long aa2 = fpack2(av, av);
                acc[i][0] = ffma2(aa2, bb.x, acc[i][0]);
                acc[i][1] = ffma2(aa2, bb.y, acc[i][1]);
            }
        }
        if (kt + 1 < nkt) {
            __syncthreads();
            int nxt = cur ^ 1;
            storeA(nxt, ar0, ra0);
            storeA(nxt, ar1, ra1);
            *(float4*)(&Bs[nxt][bkl][bnl]) = rb0;
            __syncthreads();
        }
    }

    float4 bias4 = make_float4(0.f, 0.f, 0.f, 0.f);
    if (MODE != 0) bias4 = *(const float4*)(&bias[n0 + ng * 4]);
    float al = (MODE == 2) ? alpha[0] : 0.f;

#pragma unroll
    for (int i = 0; i < 8; ++i) {
        int row = m0 + mg + i * 16;
        float2 v0 = funpack2(acc[i][0]);
        float2 v1 = funpack2(acc[i][1]);
        float4 o = make_float4(v0.x, v0.y, v1.x, v1.y);
        if (MODE == 0) {
            *(float4*)(&C[(size_t)row * Hh + n0 + ng * 4]) = o;
            size_t grow = rowbase + row;
            float4 hj = *(const float4*)(Hjp + grow * Hh + n0 + ng * 4);
            float4 e = make_float4(o.x * hj.x, o.y * hj.y, o.z * hj.z, o.w * hj.w);
            *(float4*)(&g_ctxh[grow * Hh + n0 + ng * 4]) = e;
        } else if (MODE == 1) {
            o.x = fmaxf(o.x + bias4.x, 0.f);
            o.y = fmaxf(o.y + bias4.y, 0.f);
            o.z = fmaxf(o.z + bias4.z, 0.f);
            o.w = fmaxf(o.w + bias4.w, 0.f);
            *(float4*)(&C[(size_t)row * VHID + n0 + ng * 4]) = o;
        } else {
            o.x = al * (o.x + bias4.x);
            o.y = al * (o.y + bias4.y);
            o.z = al * (o.z + bias4.z);
            o.w = al * (o.w + bias4.w);
            *(float4*)(&C[(size_t)row * Hh + n0 + ng * 4]) = o;
        }
    }
}

// ================= launch =================
extern "C" void kernel_launch(void* const* d_in, const int* in_sizes, int n_in, void* d_out,
                              int out_size) {
    const float* Hj   = (const float*)d_in[0];
    const float* Hi   = (const float*)d_in[1];
    const float* mask = (const float*)d_in[2];
    const float* Wpj  = (const float*)d_in[3];
    const float* Wpi  = (const float*)d_in[4];
    const float* W1   = (const float*)d_in[5];
    const float* b1   = (const float*)d_in[6];
    const float* W2   = (const float*)d_in[7];
    // d_in[8] = b2: constant logit shift -> cancels in softmax
    const float* Wv1   = (const float*)d_in[9];
    const float* bv1   = (const float*)d_in[10];
    const float* Wv2   = (const float*)d_in[11];
    const float* bv2   = (const float*)d_in[12];
    const float* alpha = (const float*)d_in[13];
    float* out = (float*)d_out;

    float* d_probs = nullptr;
    float* d_ctx = nullptr;
    float* d_hid = nullptr;
    cudaGetSymbolAddress((void**)&d_probs, g_probs);
    cudaGetSymbolAddress((void**)&d_ctx, g_ctx);
    cudaGetSymbolAddress((void**)&d_hid, g_hid);

    k1_prep<<<Bb * Ss, 128>>>(Hj, Hi, Wpj, Wpi, W1, b1);
    k2_pair<<<Bb * Ss, 128>>>(W1, W2, mask);
    gemm_kernel<0><<<dim3(Ss / 128, Hh / 64, Bb), 256>>>(d_probs, Hi, Hj, nullptr, nullptr,
                                                         d_ctx, Ss, Ss);
    gemm_kernel<1><<<dim3(Bb * Ss / 128, VHID / 64), 256>>>(nullptr, Wv1, Hj, bv1, nullptr, d_hid,
                                                            VIN, 0);
    gemm_kernel<2><<<dim3(Bb * Ss / 128, Hh / 64), 256>>>(d_hid, Wv2, nullptr, bv2, alpha, out,
                                                          VHID, VHID);
}

// round 5
// speedup vs baseline: 1.8618x; 1.1250x over previous
#include <cuda_runtime.h>

#define Bb   2
#define Ss   1024
#define Hh   768
#define Dd   24
#define Kk   96
#define VIN  2304
#define VHID 768

// ---------------- scratch ----------------
__device__ float g_Zj[Bb * Ss * Dd];
__device__ float g_Zi[Bb * Ss * Dd];
__device__ float g_CJ[Bb * Ss * Kk];
__device__ float g_CI[Bb * Ss * Kk];
__device__ float g_probs[(size_t)Bb * Ss * Ss];
__device__ float g_ctx[Bb * Ss * Hh];
__device__ float g_ctxh[Bb * Ss * Hh];
__device__ float g_hid[Bb * Ss * VHID];

__device__ __forceinline__ unsigned long long ffma2(unsigned long long a, unsigned long long b,
                                                    unsigned long long c) {
    unsigned long long d;
    asm("fma.rn.f32x2 %0, %1, %2, %3;" : "=l"(d) : "l"(a), "l"(b), "l"(c));
    return d;
}
__device__ __forceinline__ unsigned long long fpack2(float lo, float hi) {
    unsigned long long d;
    asm("mov.b64 %0, {%1, %2};" : "=l"(d) : "f"(lo), "f"(hi));
    return d;
}
__device__ __forceinline__ float2 funpack2(unsigned long long a) {
    float2 r;
    asm("mov.b64 {%0, %1}, %2;" : "=f"(r.x), "=f"(r.y) : "l"(a));
    return r;
}

// ================= K1: Zj, Zi, cj = b1 + Zj@W1a, ci = Zi@W1b =================
__global__ __launch_bounds__(128) void k1_prep(const float* __restrict__ Hj,
                                               const float* __restrict__ Hi,
                                               const float* __restrict__ Wpj,
                                               const float* __restrict__ Wpi,
                                               const float* __restrict__ W1,
                                               const float* __restrict__ b1) {
    int bs  = blockIdx.x;
    int tid = threadIdx.x;
    int w   = tid >> 5, l = tid & 31;
    __shared__ float part[4][Dd];
    __shared__ float zjs[Dd], zis[Dd];

    const float* Hrow = (w < 2 ? Hj : Hi) + (size_t)bs * Hh;
    const float* Wp   = (w < 2 ? Wpj : Wpi);
    if (l < Dd) {
        float acc = 0.f;
        int h0 = (w & 1) * (Hh / 2);
#pragma unroll 4
        for (int h = h0; h < h0 + Hh / 2; ++h)
            acc = fmaf(Hrow[h], Wp[h * Dd + l], acc);
        part[w][l] = acc;
    }
    __syncthreads();
    if (tid < Dd) {
        float z = part[0][tid] + part[1][tid];
        zjs[tid] = z;
        g_Zj[bs * Dd + tid] = z;
    }
    if (tid >= 32 && tid < 32 + Dd) {
        int d = tid - 32;
        float z = part[2][d] + part[3][d];
        zis[d] = z;
        g_Zi[bs * Dd + d] = z;
    }
    __syncthreads();
    if (tid < Kk) {
        float cj = b1[tid], ci = 0.f;
#pragma unroll
        for (int d = 0; d < Dd; ++d) {
            cj = fmaf(zjs[d], W1[d * Kk + tid], cj);
            ci = fmaf(zis[d], W1[(Dd + d) * Kk + tid], ci);
        }
        g_CJ[bs * Kk + tid] = cj;
        g_CI[bs * Kk + tid] = ci;
    }
}

// ================= K2: pairwise logits + softmax -> probs =================
__global__ __launch_bounds__(128) void k2_pair(const float* __restrict__ W1,
                                               const float* __restrict__ W2,
                                               const float* __restrict__ mask) {
    int bs  = blockIdx.x;
    int b   = bs >> 10;
    int tid = threadIdx.x;

    __shared__ __align__(16) float w1c_t[Kk][Dd];
    __shared__ __align__(16) float w1d_t[Kk][Dd];
    __shared__ float w2s[Kk], cjs[Kk], zjs[Dd];
    __shared__ float lg[Ss];
    __shared__ float red[4];

    for (int idx = tid; idx < Kk * Dd; idx += 128) {
        int k = idx / Dd, d = idx - k * Dd;
        w1c_t[k][d] = W1[(2 * Dd + d) * Kk + k];
        w1d_t[k][d] = W1[(3 * Dd + d) * Kk + k];
    }
    if (tid < Kk) {
        w2s[tid] = W2[tid];
        cjs[tid] = g_CJ[bs * Kk + tid];
    }
    if (tid < Dd) zjs[tid] = g_Zj[bs * Dd + tid];
    __syncthreads();

    float zj[Dd];
#pragma unroll
    for (int d = 0; d < Dd; ++d) zj[d] = zjs[d];

    const float* ciBase = g_CI + (size_t)b * Ss * Kk;
    const float* ziBase = g_Zi + (size_t)b * Ss * Dd;

#pragma unroll 1
    for (int it = 0; it < 4; ++it) {
        int ta = it * 256 + tid * 2;
        int tb = ta + 1;

        float zA[Dd], zB[Dd];
        {
            const float4* ra = (const float4*)(ziBase + (size_t)ta * Dd);
            const float4* rb = (const float4*)(ziBase + (size_t)tb * Dd);
#pragma unroll
            for (int q = 0; q < Dd / 4; ++q) {
                float4 va = ra[q], vb = rb[q];
                zA[4 * q] = va.x; zA[4 * q + 1] = va.y; zA[4 * q + 2] = va.z; zA[4 * q + 3] = va.w;
                zB[4 * q] = vb.x; zB[4 * q + 1] = vb.y; zB[4 * q + 2] = vb.z; zB[4 * q + 3] = vb.w;
            }
        }
        unsigned long long pa[Dd / 2], aa[Dd / 2], pb[Dd / 2], ab[Dd / 2];
#pragma unroll
        for (int q = 0; q < Dd / 2; ++q) {
            float j0 = zj[2 * q], j1 = zj[2 * q + 1];
            pa[q] = fpack2(j0 * zA[2 * q], j1 * zA[2 * q + 1]);
            aa[q] = fpack2(fabsf(j0 - zA[2 * q]), fabsf(j1 - zA[2 * q + 1]));
            pb[q] = fpack2(j0 * zB[2 * q], j1 * zB[2 * q + 1]);
            ab[q] = fpack2(fabsf(j0 - zB[2 * q]), fabsf(j1 - zB[2 * q + 1]));
        }

        const float* ciA = ciBase + (size_t)ta * Kk;
        const float* ciB = ciBase + (size_t)tb * Kk;
        float logitA = 0.f, logitB = 0.f;

#pragma unroll 1
        for (int k4 = 0; k4 < Kk; k4 += 4) {
            float4 cA4 = *(const float4*)(ciA + k4);
            float4 cB4 = *(const float4*)(ciB + k4);
            float cAv[4] = {cA4.x, cA4.y, cA4.z, cA4.w};
            float cBv[4] = {cB4.x, cB4.y, cB4.z, cB4.w};
#pragma unroll
            for (int j = 0; j < 4; ++j) {
                int k = k4 + j;
                const ulonglong2* wc = (const ulonglong2*)(&w1c_t[k][0]);
                const ulonglong2* wd = (const ulonglong2*)(&w1d_t[k][0]);
                unsigned long long sA = 0ull, sB = 0ull;
#pragma unroll
                for (int u = 0; u < 6; ++u) {
                    ulonglong2 c = wc[u];
                    sA = ffma2(pa[2 * u], c.x, sA);
                    sA = ffma2(pa[2 * u + 1], c.y, sA);
                    sB = ffma2(pb[2 * u], c.x, sB);
                    sB = ffma2(pb[2 * u + 1], c.y, sB);
                }
#pragma unroll
                for (int u = 0; u < 6; ++u) {
                    ulonglong2 c = wd[u];
                    sA = ffma2(aa[2 * u], c.x, sA);
                    sA = ffma2(aa[2 * u + 1], c.y, sA);
                    sB = ffma2(ab[2 * u], c.x, sB);
                    sB = ffma2(ab[2 * u + 1], c.y, sB);
                }
                float2 uA = funpack2(sA);
                float2 uB = funpack2(sB);
                float hA = (uA.x + uA.y) + (cjs[k] + cAv[j]);
                float hB = (uB.x + uB.y) + (cjs[k] + cBv[j]);
                hA = fmaxf(hA, 0.f);
                hB = fmaxf(hB, 0.f);
                logitA = fmaf(hA, w2s[k], logitA);
                logitB = fmaf(hB, w2s[k], logitB);
            }
        }
        float mA = mask[b * Ss + ta];
        float mB = mask[b * Ss + tb];
        lg[ta] = logitA + (1.0f - mA) * (-3.402823466e38f);
        lg[tb] = logitB + (1.0f - mB) * (-3.402823466e38f);
    }
    __syncthreads();

    float mx = -3.402823466e38f;
    for (int i = tid; i < Ss; i += 128) mx = fmaxf(mx, lg[i]);
#pragma unroll
    for (int o = 16; o; o >>= 1) mx = fmaxf(mx, __shfl_xor_sync(0xffffffffu, mx, o));
    if ((tid & 31) == 0) red[tid >> 5] = mx;
    __syncthreads();
    mx = fmaxf(fmaxf(red[0], red[1]), fmaxf(red[2], red[3]));
    __syncthreads();

    float sum = 0.f;
    for (int i = tid; i < Ss; i += 128) {
        float e = __expf(lg[i] - mx);
        lg[i] = e;
        sum += e;
    }
#pragma unroll
    for (int o = 16; o; o >>= 1) sum += __shfl_xor_sync(0xffffffffu, sum, o);
    if ((tid & 31) == 0) red[tid >> 5] = sum;
    __syncthreads();
    sum = (red[0] + red[1]) + (red[2] + red[3]);
    float inv = 1.0f / sum;

    float* orow = g_probs + (size_t)bs * Ss;
    for (int i = tid; i < Ss; i += 128) orow[i] = lg[i] * inv;
}

// ====== GEMM: 128x96 tile, 256 thr, micro = 4 row-pairs x 6 cols, f32x2 packed ======
// Smem: A as row-pair-packed u64 (LDS.64 -> ready operand), B pre-duplicated (b,b) u64.
// MODE 0: ctx = probs @ H_i (per b); epilogue also writes ctxh = ctx * Hj
// MODE 1: hid = relu([ctx|Hj|ctxh] @ Wv1 + bv1)
// MODE 2: out = alpha * (hid @ Wv2 + bv2)
template <int MODE>
__global__ __launch_bounds__(256) void gemm_kernel(const float* __restrict__ Ap,
                                                   const float* __restrict__ Bp,
                                                   const float* __restrict__ Hjp,
                                                   const float* __restrict__ bias,
                                                   const float* __restrict__ alpha,
                                                   float* __restrict__ Cp, int Kdim, int lda) {
    const int m0 = blockIdx.x * 128;
    const int n0 = blockIdx.y * 96;
    const float* A = Ap;
    const float* Bm = Bp;
    float* C = Cp;
    size_t rowbase = 0;
    if (MODE == 0) {
        int b = blockIdx.z;
        A += (size_t)b * Ss * Ss;
        Bm += (size_t)b * Ss * Hh;
        C += (size_t)b * Ss * Hh;
        rowbase = (size_t)b * Ss;
    }

    // As2[kk][m2]: f32x2 of rows (2*m2, 2*m2+1) at k=kk. 65-pad: LDS.64 conflict-free.
    __shared__ unsigned long long As2[2][16][65];
    // Bs2[kk][n]: (b,b) duplicated. 98-pad: row byte stride 784 = 16B multiple -> LDS.128 ok.
    __shared__ __align__(16) unsigned long long Bs2[2][16][98];

    const int tid = threadIdx.x;
    const int mg = tid & 15;        // row-pair group: m2 = mg + 16q
    const int ng = tid >> 4;        // col group: cols ng*6 .. ng*6+5
    const int ar0 = tid >> 2, ar1 = ar0 + 64;
    const int ac  = (tid & 3) * 4;  // k offset of the float4
    const int b0r = tid / 24, b0c = (tid % 24) * 4;
    const int i1  = tid + 256;
    const int b1r = i1 / 24, b1c = (i1 % 24) * 4;
    const bool hasB1 = (tid < 128);

    unsigned long long acc[4][6];
#pragma unroll
    for (int q = 0; q < 4; ++q)
#pragma unroll
        for (int j = 0; j < 6; ++j) acc[q][j] = 0ull;

    const int nkt = Kdim / 16;

    float4 pa0, pa1, pb0, pb1;

    auto loadAB = [&](int k0) {
        int kc = k0 + ac;
        if (MODE == 1) {
            int seg = kc / Hh;  // uniform within slab (Hh % 16 == 0)
            const float* base = (seg == 0) ? g_ctx : (seg == 1) ? Hjp : g_ctxh;
            int kq = kc - seg * Hh;
            pa0 = *(const float4*)(base + (size_t)(m0 + ar0) * Hh + kq);
            pa1 = *(const float4*)(base + (size_t)(m0 + ar1) * Hh + kq);
        } else {
            pa0 = *(const float4*)(A + (size_t)(m0 + ar0) * lda + kc);
            pa1 = *(const float4*)(A + (size_t)(m0 + ar1) * lda + kc);
        }
        pb0 = *(const float4*)(Bm + (size_t)(k0 + b0r) * Hh + n0 + b0c);
        if (hasB1) pb1 = *(const float4*)(Bm + (size_t)(k0 + b1r) * Hh + n0 + b1c);
    };

    auto storeAB = [&](int buf) {
        float* ap = (float*)&As2[buf][0][0];
        int m2a = ar0 >> 1, ha = ar0 & 1;
        int m2b = ar1 >> 1, hb = ar1 & 1;
        const float va[4] = {pa0.x, pa0.y, pa0.z, pa0.w};
        const float vb[4] = {pa1.x, pa1.y, pa1.z, pa1.w};
#pragma unroll
        for (int j = 0; j < 4; ++j) {
            ap[(ac + j) * 130 + m2a * 2 + ha] = va[j];
            ap[(ac + j) * 130 + m2b * 2 + hb] = vb[j];
        }
        unsigned long long* bp = &Bs2[buf][0][0];
        const float w0[4] = {pb0.x, pb0.y, pb0.z, pb0.w};
#pragma unroll
        for (int j = 0; j < 4; ++j) bp[b0r * 98 + b0c + j] = fpack2(w0[j], w0[j]);
        if (hasB1) {
            const float w1[4] = {pb1.x, pb1.y, pb1.z, pb1.w};
#pragma unroll
            for (int j = 0; j < 4; ++j) bp[b1r * 98 + b1c + j] = fpack2(w1[j], w1[j]);
        }
    };

    loadAB(0);
    storeAB(0);
    __syncthreads();

#pragma unroll 1
    for (int kt = 0; kt < nkt; ++kt) {
        const int cur = kt & 1;
        const bool more = (kt + 1 < nkt);
        if (more) loadAB((kt + 1) * 16);
#pragma unroll
        for (int kk = 0; kk < 16; ++kk) {
            unsigned long long a0 = As2[cur][kk][mg];
            unsigned long long a1 = As2[cur][kk][mg + 16];
            unsigned long long a2 = As2[cur][kk][mg + 32];
            unsigned long long a3 = As2[cur][kk][mg + 48];
            const ulonglong2* bq = (const ulonglong2*)(&Bs2[cur][kk][ng * 6]);
            ulonglong2 b01 = bq[0], b23 = bq[1], b45 = bq[2];
            acc[0][0] = ffma2(a0, b01.x, acc[0][0]);
            acc[0][1] = ffma2(a0, b01.y, acc[0][1]);
            acc[0][2] = ffma2(a0, b23.x, acc[0][2]);
            acc[0][3] = ffma2(a0, b23.y, acc[0][3]);
            acc[0][4] = ffma2(a0, b45.x, acc[0][4]);
            acc[0][5] = ffma2(a0, b45.y, acc[0][5]);
            acc[1][0] = ffma2(a1, b01.x, acc[1][0]);
            acc[1][1] = ffma2(a1, b01.y, acc[1][1]);
            acc[1][2] = ffma2(a1, b23.x, acc[1][2]);
            acc[1][3] = ffma2(a1, b23.y, acc[1][3]);
            acc[1][4] = ffma2(a1, b45.x, acc[1][4]);
            acc[1][5] = ffma2(a1, b45.y, acc[1][5]);
            acc[2][0] = ffma2(a2, b01.x, acc[2][0]);
            acc[2][1] = ffma2(a2, b01.y, acc[2][1]);
            acc[2][2] = ffma2(a2, b23.x, acc[2][2]);
            acc[2][3] = ffma2(a2, b23.y, acc[2][3]);
            acc[2][4] = ffma2(a2, b45.x, acc[2][4]);
            acc[2][5] = ffma2(a2, b45.y, acc[2][5]);
            acc[3][0] = ffma2(a3, b01.x, acc[3][0]);
            acc[3][1] = ffma2(a3, b01.y, acc[3][1]);
            acc[3][2] = ffma2(a3, b23.x, acc[3][2]);
            acc[3][3] = ffma2(a3, b23.y, acc[3][3]);
            acc[3][4] = ffma2(a3, b45.x, acc[3][4]);
            acc[3][5] = ffma2(a3, b45.y, acc[3][5]);
        }
        if (more) {
            storeAB(cur ^ 1);   // safe: writes buffer last READ before previous sync
            __syncthreads();
        }
    }

    // ---------------- epilogue ----------------
    const int col = n0 + ng * 6;
    float bs6[6];
    if (MODE != 0) {
#pragma unroll
        for (int j = 0; j < 6; ++j) bs6[j] = bias[col + j];
    }
    float al = (MODE == 2) ? alpha[0] : 0.f;

#pragma unroll
    for (int q = 0; q < 4; ++q) {
        int r = m0 + 2 * (mg + 16 * q);  // rows r, r+1
        float lo[6], hi[6];
#pragma unroll
        for (int j = 0; j < 6; ++j) {
            float2 u = funpack2(acc[q][j]);
            lo[j] = u.x;
            hi[j] = u.y;
        }
        if (MODE == 0) {
            size_t g0r = rowbase + r, g1r = g0r + 1;
#pragma unroll
            for (int j = 0; j < 6; ++j) {
                C[(size_t)r * Hh + col + j]       = lo[j];
                C[(size_t)(r + 1) * Hh + col + j] = hi[j];
                float h0 = Hjp[g0r * Hh + col + j];
                float h1 = Hjp[g1r * Hh + col + j];
                g_ctxh[g0r * Hh + col + j] = lo[j] * h0;
                g_ctxh[g1r * Hh + col + j] = hi[j] * h1;
            }
        } else if (MODE == 1) {
#pragma unroll
            for (int j = 0; j < 6; ++j) {
                C[(size_t)r * VHID + col + j]       = fmaxf(lo[j] + bs6[j], 0.f);
                C[(size_t)(r + 1) * VHID + col + j] = fmaxf(hi[j] + bs6[j], 0.f);
            }
        } else {
#pragma unroll
            for (int j = 0; j < 6; ++j) {
                C[(size_t)r * Hh + col + j]       = al * (lo[j] + bs6[j]);
                C[(size_t)(r + 1) * Hh + col + j] = al * (hi[j] + bs6[j]);
            }
        }
    }
}

// ================= launch =================
extern "C" void kernel_launch(void* const* d_in, const int* in_sizes, int n_in, void* d_out,
                              int out_size) {
    const float* Hj   = (const float*)d_in[0];
    const float* Hi   = (const float*)d_in[1];
    const float* mask = (const float*)d_in[2];
    const float* Wpj  = (const float*)d_in[3];
    const float* Wpi  = (const float*)d_in[4];
    const float* W1   = (const float*)d_in[5];
    const float* b1   = (const float*)d_in[6];
    const float* W2   = (const float*)d_in[7];
    // d_in[8] = b2: constant logit shift -> cancels in softmax
    const float* Wv1   = (const float*)d_in[9];
    const float* bv1   = (const float*)d_in[10];
    const float* Wv2   = (const float*)d_in[11];
    const float* bv2   = (const float*)d_in[12];
    const float* alpha = (const float*)d_in[13];
    float* out = (float*)d_out;

    float* d_probs = nullptr;
    float* d_ctx = nullptr;
    float* d_hid = nullptr;
    cudaGetSymbolAddress((void**)&d_probs, g_probs);
    cudaGetSymbolAddress((void**)&d_ctx, g_ctx);
    cudaGetSymbolAddress((void**)&d_hid, g_hid);

    k1_prep<<<Bb * Ss, 128>>>(Hj, Hi, Wpj, Wpi, W1, b1);
    k2_pair<<<Bb * Ss, 128>>>(W1, W2, mask);
    gemm_kernel<0><<<dim3(Ss / 128, Hh / 96, Bb), 256>>>(d_probs, Hi, Hj, nullptr, nullptr,
                                                         d_ctx, Ss, Ss);
    gemm_kernel<1><<<dim3(Bb * Ss / 128, VHID / 96), 256>>>(nullptr, Wv1, Hj, bv1, nullptr, d_hid,
                                                            VIN, 0);
    gemm_kernel<2><<<dim3(Bb * Ss / 128, Hh / 96), 256>>>(d_hid, Wv2, nullptr, bv2, alpha, out,
                                                          VHID, VHID);
}